// round 2
// baseline (speedup 1.0000x reference)
#include <cuda_runtime.h>
#include <cstdint>

#define B_  32
#define T_  512
#define D_  2048
#define H_  128
#define G_  512
#define M_FWD (B_ * T_)      // 16384

// ---------------- scratch (device globals: no allocations allowed) ----------
__device__ float g_xp[M_FWD * G_];      // forward gate preactivations  [B*T, 4H]
__device__ float g_gb[B_ * G_];         // backward gate preacts at t=T-1 [B, 4H]
__device__ float g_last[B_ * 2 * H_];   // [h_fwd(T-1) | h_bwd(T-1)]     [B, 2H]

extern __shared__ unsigned char dynsmem[];

__device__ __forceinline__ uint32_t f2tf32(float x) {
    uint32_t u;
    asm("cvt.rna.tf32.f32 %0, %1;" : "=r"(u) : "f"(x));
    return u;
}

__device__ __forceinline__ float sigmoidf_(float x) {
    return 1.0f / (1.0f + expf(-x));
}

// ============================================================================
// tf32 GEMM: C[M x 512] = A[M x 2048] @ W^T + bias0 + bias1
//   A: row stride lda (elements), rows >= Mreal are treated as zero
//   W: [512][2048] row-major (i.e. both operands K-contiguous -> mma row.col)
//   C: row-major, ldc = 512
// Tiles: BM=128, BN=128, BK=32; 256 threads = 8 warps (4 m x 2 n),
// warp tile 32x64, mma m16n8k8 tf32. Double-buffered smem via register staging.
// ============================================================================
__global__ __launch_bounds__(256)
void gemm_tf32(const float* __restrict__ A, int lda, int Mreal,
               const float* __restrict__ W,
               const float* __restrict__ bias0, const float* __restrict__ bias1,
               float* __restrict__ C)
{
    constexpr int BK = 32, PK = 36;          // padded k-stride (conflict-free)
    constexpr int NIT = D_ / BK;             // 64 mainloop iterations
    uint32_t* As = (uint32_t*)dynsmem;       // [2][128*PK]
    uint32_t* Bs = As + 2 * 128 * PK;        // [2][128*PK]

    const int tid  = threadIdx.x;
    const int wid  = tid >> 5, lane = tid & 31;
    const int wm   = wid & 3,  wn   = wid >> 2;     // warp grid 4 x 2
    const int g    = lane >> 2, tg  = lane & 3;
    const int m0   = blockIdx.x * 128, n0 = blockIdx.y * 128;

    const int lr = tid >> 3;          // 0..31 : row within a 32-row group
    const int lc = (tid & 7) * 4;     // 0,4,...,28 : k offset (float4)

    float4 ra[4], rb[4];
    float acc[2][8][4];
    #pragma unroll
    for (int i = 0; i < 2; i++)
        #pragma unroll
        for (int j = 0; j < 8; j++)
            #pragma unroll
            for (int r = 0; r < 4; r++) acc[i][j][r] = 0.0f;

    // ---- prologue: load tile 0 -> regs -> smem buf 0 ----
    {
        const int k = 0 + lc;
        #pragma unroll
        for (int i = 0; i < 4; i++) {
            const int r  = lr + i * 32;
            const int gm = m0 + r;
            if (gm < Mreal) ra[i] = *(const float4*)(A + (long)gm * lda + k);
            else            ra[i] = make_float4(0.f, 0.f, 0.f, 0.f);
            rb[i] = *(const float4*)(W + (n0 + r) * D_ + k);
        }
        uint32_t* as = As;
        uint32_t* bs = Bs;
        #pragma unroll
        for (int i = 0; i < 4; i++) {
            const int r = lr + i * 32;
            uint32_t* pa = as + r * PK + lc;
            pa[0] = f2tf32(ra[i].x); pa[1] = f2tf32(ra[i].y);
            pa[2] = f2tf32(ra[i].z); pa[3] = f2tf32(ra[i].w);
            uint32_t* pb = bs + r * PK + lc;
            pb[0] = f2tf32(rb[i].x); pb[1] = f2tf32(rb[i].y);
            pb[2] = f2tf32(rb[i].z); pb[3] = f2tf32(rb[i].w);
        }
    }
    __syncthreads();

    for (int it = 0; it < NIT; it++) {
        const int cur = it & 1;

        // ---- stage next tile into registers (global loads fly during mma) ----
        if (it + 1 < NIT) {
            const int k = (it + 1) * BK + lc;
            #pragma unroll
            for (int i = 0; i < 4; i++) {
                const int r  = lr + i * 32;
                const int gm = m0 + r;
                if (gm < Mreal) ra[i] = *(const float4*)(A + (long)gm * lda + k);
                else            ra[i] = make_float4(0.f, 0.f, 0.f, 0.f);
                rb[i] = *(const float4*)(W + (n0 + r) * D_ + k);
            }
        }

        // ---- compute on current buffer ----
        {
            const uint32_t* as = As + cur * 128 * PK;
            const uint32_t* bs = Bs + cur * 128 * PK;
            #pragma unroll
            for (int kk = 0; kk < 4; kk++) {
                uint32_t af[2][4], bf[8][2];
                #pragma unroll
                for (int mf = 0; mf < 2; mf++) {
                    const int r0 = wm * 32 + mf * 16;
                    const uint32_t* p = as + r0 * PK + kk * 8 + tg;
                    af[mf][0] = p[g * PK];
                    af[mf][1] = p[(8 + g) * PK];
                    af[mf][2] = p[g * PK + 4];
                    af[mf][3] = p[(8 + g) * PK + 4];
                }
                #pragma unroll
                for (int nf = 0; nf < 8; nf++) {
                    const int c0 = wn * 64 + nf * 8;
                    const uint32_t* p = bs + (c0 + g) * PK + kk * 8 + tg;
                    bf[nf][0] = p[0];
                    bf[nf][1] = p[4];
                }
                #pragma unroll
                for (int mf = 0; mf < 2; mf++)
                    #pragma unroll
                    for (int nf = 0; nf < 8; nf++)
                        asm volatile(
                            "mma.sync.aligned.m16n8k8.row.col.f32.tf32.tf32.f32 "
                            "{%0,%1,%2,%3}, {%4,%5,%6,%7}, {%8,%9}, {%0,%1,%2,%3};"
                            : "+f"(acc[mf][nf][0]), "+f"(acc[mf][nf][1]),
                              "+f"(acc[mf][nf][2]), "+f"(acc[mf][nf][3])
                            : "r"(af[mf][0]), "r"(af[mf][1]),
                              "r"(af[mf][2]), "r"(af[mf][3]),
                              "r"(bf[nf][0]), "r"(bf[nf][1]));
            }
        }

        // ---- drain staged tile into the other buffer ----
        if (it + 1 < NIT) {
            const int nb = (it + 1) & 1;
            uint32_t* as = As + nb * 128 * PK;
            uint32_t* bs = Bs + nb * 128 * PK;
            #pragma unroll
            for (int i = 0; i < 4; i++) {
                const int r = lr + i * 32;
                uint32_t* pa = as + r * PK + lc;
                pa[0] = f2tf32(ra[i].x); pa[1] = f2tf32(ra[i].y);
                pa[2] = f2tf32(ra[i].z); pa[3] = f2tf32(ra[i].w);
                uint32_t* pb = bs + r * PK + lc;
                pb[0] = f2tf32(rb[i].x); pb[1] = f2tf32(rb[i].y);
                pb[2] = f2tf32(rb[i].z); pb[3] = f2tf32(rb[i].w);
            }
        }
        __syncthreads();
    }

    // ---- epilogue: add both biases, store ----
    #pragma unroll
    for (int mf = 0; mf < 2; mf++) {
        #pragma unroll
        for (int nf = 0; nf < 8; nf++) {
            const int col = n0 + wn * 64 + nf * 8 + 2 * tg;
            const float bs0 = bias0[col]     + bias1[col];
            const float bs1 = bias0[col + 1] + bias1[col + 1];
            const int r0 = m0 + wm * 32 + mf * 16 + g;
            if (r0 < Mreal) {
                float2 v; v.x = acc[mf][nf][0] + bs0; v.y = acc[mf][nf][1] + bs1;
                *(float2*)(C + (long)r0 * G_ + col) = v;
            }
            const int r1 = r0 + 8;
            if (r1 < Mreal) {
                float2 v; v.x = acc[mf][nf][2] + bs0; v.y = acc[mf][nf][3] + bs1;
                *(float2*)(C + (long)r1 * G_ + col) = v;
            }
        }
    }
}

// ============================================================================
// Forward LSTM recurrence: one CTA per batch element, 512 threads
// (thread j owns gate row j). W_hh rows [0,416) live in smem (row stride 132
// floats -> conflict-free LDS.128); rows [416,512) (warps 13..15) stream from
// L2 (same lines shared by all 32 CTAs). No inter-CTA sync anywhere.
// ============================================================================
#define SMROWS 416
#define WPAD   132

__global__ __launch_bounds__(512)
void lstm_fwd(const float* __restrict__ xp, const float* __restrict__ Whh,
              float* __restrict__ last)
{
    float* W_s    = (float*)dynsmem;             // [SMROWS][WPAD]
    float* h_s    = W_s + SMROWS * WPAD;         // [128]
    float* gate_s = h_s + 128;                   // [512]

    const int tid = threadIdx.x;
    const int b   = blockIdx.x;

    // stage W_hh rows [0, SMROWS) into padded smem (coalesced gmem reads)
    for (int idx = tid; idx < SMROWS * 128; idx += 512) {
        const int j = idx >> 7, k = idx & 127;
        W_s[j * WPAD + k] = Whh[idx];
    }
    if (tid < 128) h_s[tid] = 0.0f;
    float c = 0.0f;
    __syncthreads();

    const float*  xprow = xp + (long)b * T_ * G_;
    const float4* wp    = (const float4*)(W_s + tid * WPAD);       // smem rows
    const float4* wg    = (const float4*)(Whh + tid * 128);        // gmem rows

    for (int t = 0; t < T_; t++) {
        float acc = xprow[t * G_ + tid];
        if (tid < SMROWS) {
            #pragma unroll
            for (int k4 = 0; k4 < 32; k4++) {
                const float4 w  = wp[k4];
                const float4 hh = *(const float4*)(h_s + k4 * 4);  // broadcast
                acc += w.x * hh.x + w.y * hh.y + w.z * hh.z + w.w * hh.w;
            }
        } else {
            #pragma unroll
            for (int k4 = 0; k4 < 32; k4++) {
                const float4 w  = __ldg(wg + k4);
                const float4 hh = *(const float4*)(h_s + k4 * 4);
                acc += w.x * hh.x + w.y * hh.y + w.z * hh.z + w.w * hh.w;
            }
        }
        gate_s[tid] = acc;
        __syncthreads();
        if (tid < 128) {
            const float gi = gate_s[tid],       gf = gate_s[128 + tid];
            const float gg = gate_s[256 + tid], go = gate_s[384 + tid];
            c = sigmoidf_(gf) * c + sigmoidf_(gi) * tanhf(gg);
            const float h = sigmoidf_(go) * tanhf(c);
            h_s[tid] = h;
            if (t == T_ - 1) last[b * (2 * H_) + tid] = h;
        }
        __syncthreads();
    }
}

// ============================================================================
// Backward direction, single step from zero state (reverse scan output at
// t = T-1):  c = sig(i)*tanh(g),  h = sig(o)*tanh(c).  Forget gate * c0 = 0.
// ============================================================================
__global__ void bwd_last(const float* __restrict__ gb, float* __restrict__ last)
{
    const int b = blockIdx.x, j = threadIdx.x;   // 32 x 128
    const float* r = gb + b * G_;
    const float ci = sigmoidf_(r[j]) * tanhf(r[256 + j]);
    last[b * (2 * H_) + H_ + j] = sigmoidf_(r[384 + j]) * tanhf(ci);
}

// ============================================================================
// MLP head + softmax: one CTA per batch row (tiny).
// ============================================================================
__global__ void head_kernel(const float* __restrict__ last,
                            const float* __restrict__ W1, const float* __restrict__ b1,
                            const float* __restrict__ W2, const float* __restrict__ b2,
                            const float* __restrict__ W3, const float* __restrict__ b3,
                            float* __restrict__ out)
{
    __shared__ float v[256], u[256], w2s[64], lg[11];
    const int b = blockIdx.x, tid = threadIdx.x;   // 256 threads

    v[tid] = last[b * 256 + tid];
    __syncthreads();

    float a = b1[tid];
    #pragma unroll 8
    for (int k = 0; k < 256; k++) a += W1[tid * 256 + k] * v[k];
    u[tid] = a;
    __syncthreads();

    if (tid < 64) {
        float s = b2[tid];
        #pragma unroll 8
        for (int k = 0; k < 256; k++) s += W2[tid * 256 + k] * u[k];
        w2s[tid] = s;
    }
    __syncthreads();

    if (tid < 11) {
        float s = b3[tid];
        #pragma unroll
        for (int k = 0; k < 64; k++) s += W3[tid * 64 + k] * w2s[k];
        lg[tid] = s;
    }
    __syncthreads();

    if (tid == 0) {
        float mx = lg[0];
        for (int i = 1; i < 11; i++) mx = fmaxf(mx, lg[i]);
        float e[11], sum = 0.0f;
        for (int i = 0; i < 11; i++) { e[i] = expf(lg[i] - mx); sum += e[i]; }
        const float inv = 1.0f / sum;
        for (int i = 0; i < 11; i++) out[b * 11 + i] = e[i] * inv;
    }
}

// ============================================================================
extern "C" void kernel_launch(void* const* d_in, const int* in_sizes, int n_in,
                              void* d_out, int out_size)
{
    const float* x    = (const float*)d_in[0];
    const float* Wihf = (const float*)d_in[1];
    const float* Whhf = (const float*)d_in[2];
    const float* bihf = (const float*)d_in[3];
    const float* bhhf = (const float*)d_in[4];
    const float* Wihb = (const float*)d_in[5];
    const float* Whhb = (const float*)d_in[6];  (void)Whhb;  // h0=0: unused
    const float* bihb = (const float*)d_in[7];
    const float* bhhb = (const float*)d_in[8];
    const float* W1 = (const float*)d_in[9];   const float* b1 = (const float*)d_in[10];
    const float* W2 = (const float*)d_in[11];  const float* b2 = (const float*)d_in[12];
    const float* W3 = (const float*)d_in[13];  const float* b3 = (const float*)d_in[14];
    float* out = (float*)d_out;

    void* p;
    cudaGetSymbolAddress(&p, g_xp);   float* xp   = (float*)p;
    cudaGetSymbolAddress(&p, g_gb);   float* gb   = (float*)p;
    cudaGetSymbolAddress(&p, g_last); float* last = (float*)p;

    const int gemm_smem = 2 * 2 * 128 * 36 * (int)sizeof(uint32_t);   // 73728
    const int lstm_smem = (SMROWS * WPAD + 128 + 512) * (int)sizeof(float); // 222208
    cudaFuncSetAttribute(gemm_tf32, cudaFuncAttributeMaxDynamicSharedMemorySize, gemm_smem);
    cudaFuncSetAttribute(lstm_fwd,  cudaFuncAttributeMaxDynamicSharedMemorySize, lstm_smem);

    // forward input projection: [16384 x 2048] @ W_ih_f^T + b_ih_f + b_hh_f
    dim3 gf(M_FWD / 128, G_ / 128);
    gemm_tf32<<<gf, 256, gemm_smem>>>(x, D_, M_FWD, Wihf, bihf, bhhf, xp);

    // backward direction needs only t = T-1 rows: A row b at x[b][T-1][:]
    dim3 gbk(1, G_ / 128);
    gemm_tf32<<<gbk, 256, gemm_smem>>>(x + (long)(T_ - 1) * D_, T_ * D_, B_,
                                       Wihb, bihb, bhhb, gb);

    bwd_last<<<B_, 128>>>(gb, last);
    lstm_fwd<<<B_, 512, lstm_smem>>>(xp, Whhf, last);
    head_kernel<<<B_, 256>>>(last, W1, b1, W2, b2, W3, b3, out);
}